// round 1
// baseline (speedup 1.0000x reference)
#include <cuda_runtime.h>

// ---------------------------------------------------------------------------
// CrossModalAttention baseline: 6 strided SGEMMs + row softmax + concat copy.
// B=8, CQ=CKV=E=256, Nq=4096, Nkv=1024. All fp32.
// ---------------------------------------------------------------------------

#define BM 128
#define BN 128
#define BK 8

// Scratch (device globals; no allocation allowed)
__device__ float g_theta[(size_t)8 * 256 * 4096];   // [B,E,Nq]
__device__ float g_phi  [(size_t)8 * 256 * 1024];   // [B,E,Nkv]
__device__ float g_gv   [(size_t)8 * 256 * 1024];   // [B,E,Nkv]
__device__ float g_attn [(size_t)8 * 4096 * 1024];  // [B,Nq,Nkv]
__device__ float g_obuf [(size_t)8 * 256 * 4096];   // [B,E,Nq]

// Generic strided batched GEMM: C[m,n] = alpha * sum_k A[m,k]*B[k,n]
// A elem at A + z*aB + m*am + k*ak ; B at B + z*bB + k*bk + n*bn ;
// C at C + z*cB + m*cm + n (n contiguous). M,N multiples of 128, K of 8.
__global__ __launch_bounds__(256) void gemm_kernel(
    const float* __restrict__ A, const float* __restrict__ B,
    float* __restrict__ C,
    int K,
    long aB, long bB, long cB,
    int am, int ak, int bk, int bn, int cm, float alpha)
{
    __shared__ float As[BK][BM];
    __shared__ float Bs[BK][BN];

    const float* Ab = A + (long)blockIdx.z * aB;
    const float* Bb = B + (long)blockIdx.z * bB;
    float*       Cb = C + (long)blockIdx.z * cB;

    const int m0 = blockIdx.y * BM;
    const int n0 = blockIdx.x * BN;
    const int tid = threadIdx.x;
    const int tx = tid & 15;          // 16 cols of threads -> 8 n each
    const int ty = tid >> 4;          // 16 rows of threads -> 8 m each

    float acc[8][8];
    #pragma unroll
    for (int i = 0; i < 8; i++)
        #pragma unroll
        for (int j = 0; j < 8; j++) acc[i][j] = 0.0f;

    const bool aKfast = (ak == 1);
    const bool bKfast = (bk == 1);

    for (int kt = 0; kt < K; kt += BK) {
        // Cooperative tile load: 256 threads x 4 elems = 1024 per operand.
        #pragma unroll
        for (int l = 0; l < 4; l++) {
            int idx = tid + l * 256;
            int m, k;
            if (aKfast) { k = idx & 7;   m = idx >> 3; }
            else        { m = idx & 127; k = idx >> 7; }
            As[k][m] = Ab[(long)(m0 + m) * am + (long)(kt + k) * ak];
            int n, k2;
            if (bKfast) { k2 = idx & 7;   n = idx >> 3; }
            else        { n = idx & 127;  k2 = idx >> 7; }
            Bs[k2][n] = Bb[(long)(kt + k2) * bk + (long)(n0 + n) * bn];
        }
        __syncthreads();

        #pragma unroll
        for (int k = 0; k < BK; k++) {
            float ar[8], br[8];
            *(float4*)&ar[0] = *(const float4*)&As[k][ty * 8];
            *(float4*)&ar[4] = *(const float4*)&As[k][ty * 8 + 4];
            *(float4*)&br[0] = *(const float4*)&Bs[k][tx * 8];
            *(float4*)&br[4] = *(const float4*)&Bs[k][tx * 8 + 4];
            #pragma unroll
            for (int i = 0; i < 8; i++)
                #pragma unroll
                for (int j = 0; j < 8; j++)
                    acc[i][j] += ar[i] * br[j];
        }
        __syncthreads();
    }

    #pragma unroll
    for (int i = 0; i < 8; i++) {
        long rowoff = (long)(m0 + ty * 8 + i) * cm + n0 + tx * 8;
        #pragma unroll
        for (int j = 0; j < 8; j++)
            Cb[rowoff + j] = acc[i][j] * alpha;
    }
}

// Row softmax over contiguous rows of length 1024. One block per row.
__global__ __launch_bounds__(256) void softmax_kernel(float* __restrict__ S)
{
    float4* row = (float4*)(S + (long)blockIdx.x * 1024);
    const int tid = threadIdx.x;
    float4 v = row[tid];

    float m = fmaxf(fmaxf(v.x, v.y), fmaxf(v.z, v.w));
    #pragma unroll
    for (int o = 16; o; o >>= 1) m = fmaxf(m, __shfl_xor_sync(0xffffffffu, m, o));

    __shared__ float smax[8];
    __shared__ float ssum[8];
    if ((tid & 31) == 0) smax[tid >> 5] = m;
    __syncthreads();
    m = smax[0];
    #pragma unroll
    for (int i = 1; i < 8; i++) m = fmaxf(m, smax[i]);

    v.x = __expf(v.x - m); v.y = __expf(v.y - m);
    v.z = __expf(v.z - m); v.w = __expf(v.w - m);
    float s = v.x + v.y + v.z + v.w;
    #pragma unroll
    for (int o = 16; o; o >>= 1) s += __shfl_xor_sync(0xffffffffu, s, o);
    if ((tid & 31) == 0) ssum[tid >> 5] = s;
    __syncthreads();
    s = ssum[0];
    #pragma unroll
    for (int i = 1; i < 8; i++) s += ssum[i];

    const float inv = 1.0f / s;
    v.x *= inv; v.y *= inv; v.z *= inv; v.w *= inv;
    row[tid] = v;
}

// Copy C [B,256,4096] into first half of out [B,512,4096] (float4 units).
__global__ __launch_bounds__(256) void copy_c_kernel(
    const float4* __restrict__ src, float4* __restrict__ dst)
{
    long i = (long)blockIdx.x * 256 + threadIdx.x;   // 8 * 262144 total
    long b = i >> 18;            // / 262144
    long off = i & 262143;
    dst[b * 524288 + off] = src[i];
}

extern "C" void kernel_launch(void* const* d_in, const int* in_sizes, int n_in,
                              void* d_out, int out_size)
{
    const float* C   = (const float*)d_in[0];   // [8,256,64,64]
    const float* P   = (const float*)d_in[1];   // [8,256,32,32]
    const float* thw = (const float*)d_in[2];   // [256,256]
    const float* phw = (const float*)d_in[3];   // [256,256]
    const float* gw  = (const float*)d_in[4];   // [256,256]
    const float* ow  = (const float*)d_in[5];   // [256,256]
    float* out = (float*)d_out;                 // [8,512,64,64]

    float *theta, *phi, *gv, *attn, *obuf;
    cudaGetSymbolAddress((void**)&theta, g_theta);
    cudaGetSymbolAddress((void**)&phi,   g_phi);
    cudaGetSymbolAddress((void**)&gv,    g_gv);
    cudaGetSymbolAddress((void**)&attn,  g_attn);
    cudaGetSymbolAddress((void**)&obuf,  g_obuf);

    const dim3 blk(256);
    const long NQ = 4096, NKV = 1024, E = 256;

    // 1) theta = theta_w[E,CQ] @ C[b][CQ,Nq]   -> [B,E,Nq]
    gemm_kernel<<<dim3(32, 2, 8), blk>>>(thw, C, theta, 256,
        0, E * NQ, E * NQ,
        /*am*/256, /*ak*/1, /*bk*/4096, /*bn*/1, /*cm*/4096, 1.0f);

    // 2) phi = phi_w @ P[b] ; 3) gv = g_w @ P[b]  -> [B,E,Nkv]
    gemm_kernel<<<dim3(8, 2, 8), blk>>>(phw, P, phi, 256,
        0, E * NKV, E * NKV, 256, 1, 1024, 1, 1024, 1.0f);
    gemm_kernel<<<dim3(8, 2, 8), blk>>>(gw, P, gv, 256,
        0, E * NKV, E * NKV, 256, 1, 1024, 1, 1024, 1.0f);

    // 4) S[n,m] = sum_e theta[e,n]*phi[e,m] / 16   -> [B,Nq,Nkv]
    gemm_kernel<<<dim3(8, 32, 8), blk>>>(theta, phi, attn, 256,
        E * NQ, E * NKV, NQ * NKV,
        /*am*/1, /*ak*/4096, /*bk*/1024, /*bn*/1, /*cm*/1024, 0.0625f);

    // 5) softmax over each row of 1024
    softmax_kernel<<<8 * 4096, blk>>>(attn);

    // 6) O[e,n] = sum_m gv[e,m]*attn[n,m]   -> [B,E,Nq]
    gemm_kernel<<<dim3(32, 2, 8), blk>>>(gv, attn, obuf, 1024,
        E * NKV, NQ * NKV, E * NQ,
        /*am*/1024, /*ak*/1, /*bk*/1, /*bn*/1024, /*cm*/4096, 1.0f);

    // 7) F = out_w @ O[b] -> second half of out (channels 256..511)
    gemm_kernel<<<dim3(32, 2, 8), blk>>>(ow, obuf, out + 256L * 4096, 256,
        0, E * NQ, 512L * 4096,
        /*am*/256, /*ak*/1, /*bk*/4096, /*bn*/1, /*cm*/4096, 1.0f);

    // 8) concat: copy C into first half of out
    copy_c_kernel<<<8192, blk>>>((const float4*)C, (float4*)out);
}

// round 2
// speedup vs baseline: 2.5929x; 2.5929x over previous
#include <cuda_runtime.h>
#include <cstdint>

// ---------------------------------------------------------------------------
// CrossModalAttention: 6 strided GEMMs on TF32 warp-MMA + softmax + concat.
// B=8, CQ=CKV=E=256, Nq=4096, Nkv=1024.
// ---------------------------------------------------------------------------

#define BM 128
#define BN 128
#define BK 16
#define SPAD 132   // row stride (mod 32 == 4) -> conflict-free fragment loads

// Scratch (device globals; no allocation allowed)
__device__ float g_theta[(size_t)8 * 256 * 4096];   // [B,E,Nq]
__device__ float g_phi  [(size_t)8 * 256 * 1024];   // [B,E,Nkv]
__device__ float g_gv   [(size_t)8 * 256 * 1024];   // [B,E,Nkv]
__device__ float g_attn [(size_t)8 * 4096 * 1024];  // [B,Nq,Nkv]
__device__ float g_obuf [(size_t)8 * 256 * 4096];   // [B,E,Nq]

__device__ __forceinline__ uint32_t f2tf32(float x) {
    uint32_t u;
    asm("cvt.rna.tf32.f32 %0, %1;" : "=r"(u) : "f"(x));
    return u;
}

__device__ __forceinline__ void mma_tf32(
    float& c0, float& c1, float& c2, float& c3,
    uint32_t a0, uint32_t a1, uint32_t a2, uint32_t a3,
    uint32_t b0, uint32_t b1)
{
    asm volatile(
        "mma.sync.aligned.m16n8k8.row.col.f32.tf32.tf32.f32 "
        "{%0,%1,%2,%3}, {%4,%5,%6,%7}, {%8,%9}, {%0,%1,%2,%3};"
        : "+f"(c0), "+f"(c1), "+f"(c2), "+f"(c3)
        : "r"(a0), "r"(a1), "r"(a2), "r"(a3), "r"(b0), "r"(b1));
}

// Generic strided batched GEMM on TF32 tensor cores.
// C[m,n] = alpha * sum_k A[m,k]*B[k,n]
// A elem: A + z*aB + m*am + k*ak ; B: B + z*bB + k*bk + n*bn ;
// C: C + z*cB + m*cm + n (n contiguous). M,N mult of 128, K mult of 16.
__global__ __launch_bounds__(256, 2) void gemm_tf32_kernel(
    const float* __restrict__ A, const float* __restrict__ B,
    float* __restrict__ C,
    int K,
    long aB, long bB, long cB,
    int am, int ak, int bk, int bn, int cm, float alpha)
{
    __shared__ uint32_t As[BK][SPAD];
    __shared__ uint32_t Bs[BK][SPAD];

    const float* Ab = A + (long)blockIdx.z * aB;
    const float* Bb = B + (long)blockIdx.z * bB;
    float*       Cb = C + (long)blockIdx.z * cB;

    const int m0 = blockIdx.y * BM;
    const int n0 = blockIdx.x * BN;
    const int tid  = threadIdx.x;
    const int warp = tid >> 5;
    const int lane = tid & 31;
    const int wm = warp & 1;          // 2 warps along M (64 rows each)
    const int wn = warp >> 1;         // 4 warps along N (32 cols each)
    const int tg  = lane & 3;         // thread-in-group
    const int gid = lane >> 2;        // group id (0..7)

    const bool aKfast = (ak == 1);
    const bool bKfast = (bk == 1);

    // Precompute per-thread load offsets and smem store indices (8 each).
    int offA[8], offB[8], sA[8], sB[8];
    #pragma unroll
    for (int l = 0; l < 8; l++) {
        int idx = tid + l * 256;
        int m, k;
        if (aKfast) { k = idx & 15; m = idx >> 4; }
        else        { m = idx & 127; k = idx >> 7; }
        offA[l] = (m0 + m) * am + k * ak;
        sA[l] = k * SPAD + m;
        int n, k2;
        if (bKfast) { k2 = idx & 15; n = idx >> 4; }
        else        { n = idx & 127; k2 = idx >> 7; }
        offB[l] = k2 * bk + (n0 + n) * bn;
        sB[l] = k2 * SPAD + n;
    }

    float acc[4][4][4];
    #pragma unroll
    for (int i = 0; i < 4; i++)
        #pragma unroll
        for (int j = 0; j < 4; j++)
            #pragma unroll
            for (int r = 0; r < 4; r++) acc[i][j][r] = 0.0f;

    float pa[8], pb[8];
    // Prefetch tile 0
    #pragma unroll
    for (int l = 0; l < 8; l++) { pa[l] = Ab[offA[l]]; pb[l] = Bb[offB[l]]; }

    uint32_t* AsF = &As[0][0];
    uint32_t* BsF = &Bs[0][0];

    int kt = 0;
    for (;;) {
        __syncthreads();
        #pragma unroll
        for (int l = 0; l < 8; l++) {
            AsF[sA[l]] = f2tf32(pa[l]);
            BsF[sB[l]] = f2tf32(pb[l]);
        }
        __syncthreads();

        kt += BK;
        const bool more = (kt < K);
        if (more) {
            const int da = kt * ak, db = kt * bk;
            #pragma unroll
            for (int l = 0; l < 8; l++) {
                pa[l] = Ab[offA[l] + da];
                pb[l] = Bb[offB[l] + db];
            }
        }

        // Compute 2 k-substeps of 8
        #pragma unroll
        for (int ks = 0; ks < BK; ks += 8) {
            uint32_t af[4][4], bf[4][2];
            #pragma unroll
            for (int mt = 0; mt < 4; mt++) {
                const int mb = wm * 64 + mt * 16 + gid;
                af[mt][0] = As[ks + tg    ][mb    ];
                af[mt][1] = As[ks + tg    ][mb + 8];
                af[mt][2] = As[ks + tg + 4][mb    ];
                af[mt][3] = As[ks + tg + 4][mb + 8];
            }
            #pragma unroll
            for (int nt = 0; nt < 4; nt++) {
                const int nb = wn * 32 + nt * 8 + gid;
                bf[nt][0] = Bs[ks + tg    ][nb];
                bf[nt][1] = Bs[ks + tg + 4][nb];
            }
            #pragma unroll
            for (int mt = 0; mt < 4; mt++)
                #pragma unroll
                for (int nt = 0; nt < 4; nt++)
                    mma_tf32(acc[mt][nt][0], acc[mt][nt][1],
                             acc[mt][nt][2], acc[mt][nt][3],
                             af[mt][0], af[mt][1], af[mt][2], af[mt][3],
                             bf[nt][0], bf[nt][1]);
        }
        if (!more) break;
    }

    // Epilogue
    #pragma unroll
    for (int mt = 0; mt < 4; mt++) {
        const int row = m0 + wm * 64 + mt * 16 + gid;
        #pragma unroll
        for (int nt = 0; nt < 4; nt++) {
            const int col = n0 + wn * 32 + nt * 8 + tg * 2;
            float2 v0 = make_float2(acc[mt][nt][0] * alpha, acc[mt][nt][1] * alpha);
            float2 v1 = make_float2(acc[mt][nt][2] * alpha, acc[mt][nt][3] * alpha);
            *(float2*)&Cb[(long)row * cm + col]       = v0;
            *(float2*)&Cb[(long)(row + 8) * cm + col] = v1;
        }
    }
}

// Row softmax over contiguous rows of length 1024. One block per row.
__global__ __launch_bounds__(256) void softmax_kernel(float* __restrict__ S)
{
    float4* row = (float4*)(S + (long)blockIdx.x * 1024);
    const int tid = threadIdx.x;
    float4 v = row[tid];

    float m = fmaxf(fmaxf(v.x, v.y), fmaxf(v.z, v.w));
    #pragma unroll
    for (int o = 16; o; o >>= 1) m = fmaxf(m, __shfl_xor_sync(0xffffffffu, m, o));

    __shared__ float smax[8];
    __shared__ float ssum[8];
    if ((tid & 31) == 0) smax[tid >> 5] = m;
    __syncthreads();
    m = smax[0];
    #pragma unroll
    for (int i = 1; i < 8; i++) m = fmaxf(m, smax[i]);

    v.x = __expf(v.x - m); v.y = __expf(v.y - m);
    v.z = __expf(v.z - m); v.w = __expf(v.w - m);
    float s = v.x + v.y + v.z + v.w;
    #pragma unroll
    for (int o = 16; o; o >>= 1) s += __shfl_xor_sync(0xffffffffu, s, o);
    if ((tid & 31) == 0) ssum[tid >> 5] = s;
    __syncthreads();
    s = ssum[0];
    #pragma unroll
    for (int i = 1; i < 8; i++) s += ssum[i];

    const float inv = 1.0f / s;
    v.x *= inv; v.y *= inv; v.z *= inv; v.w *= inv;
    row[tid] = v;
}

// Copy C [B,256,4096] into first half of out [B,512,4096] (float4 units).
__global__ __launch_bounds__(256) void copy_c_kernel(
    const float4* __restrict__ src, float4* __restrict__ dst)
{
    long i = (long)blockIdx.x * 256 + threadIdx.x;   // 8 * 262144 total
    long b = i >> 18;
    long off = i & 262143;
    dst[b * 524288 + off] = src[i];
}

extern "C" void kernel_launch(void* const* d_in, const int* in_sizes, int n_in,
                              void* d_out, int out_size)
{
    const float* C   = (const float*)d_in[0];   // [8,256,64,64]
    const float* P   = (const float*)d_in[1];   // [8,256,32,32]
    const float* thw = (const float*)d_in[2];   // [256,256]
    const float* phw = (const float*)d_in[3];   // [256,256]
    const float* gw  = (const float*)d_in[4];   // [256,256]
    const float* ow  = (const float*)d_in[5];   // [256,256]
    float* out = (float*)d_out;                 // [8,512,64,64]

    float *theta, *phi, *gv, *attn, *obuf;
    cudaGetSymbolAddress((void**)&theta, g_theta);
    cudaGetSymbolAddress((void**)&phi,   g_phi);
    cudaGetSymbolAddress((void**)&gv,    g_gv);
    cudaGetSymbolAddress((void**)&attn,  g_attn);
    cudaGetSymbolAddress((void**)&obuf,  g_obuf);

    const dim3 blk(256);
    const long NQ = 4096, NKV = 1024, E = 256;

    // 1) theta = theta_w[E,CQ] @ C[b][CQ,Nq]   -> [B,E,Nq]
    gemm_tf32_kernel<<<dim3(32, 2, 8), blk>>>(thw, C, theta, 256,
        0, E * NQ, E * NQ,
        /*am*/256, /*ak*/1, /*bk*/4096, /*bn*/1, /*cm*/4096, 1.0f);

    // 2) phi = phi_w @ P[b] ; 3) gv = g_w @ P[b]  -> [B,E,Nkv]
    gemm_tf32_kernel<<<dim3(8, 2, 8), blk>>>(phw, P, phi, 256,
        0, E * NKV, E * NKV, 256, 1, 1024, 1, 1024, 1.0f);
    gemm_tf32_kernel<<<dim3(8, 2, 8), blk>>>(gw, P, gv, 256,
        0, E * NKV, E * NKV, 256, 1, 1024, 1, 1024, 1.0f);

    // 4) S[n,m] = sum_e theta[e,n]*phi[e,m] / 16   -> [B,Nq,Nkv]
    gemm_tf32_kernel<<<dim3(8, 32, 8), blk>>>(theta, phi, attn, 256,
        E * NQ, E * NKV, NQ * NKV,
        /*am*/1, /*ak*/4096, /*bk*/1024, /*bn*/1, /*cm*/1024, 0.0625f);

    // 5) softmax over each row of 1024
    softmax_kernel<<<8 * 4096, blk>>>(attn);

    // 6) O[e,n] = sum_m gv[e,m]*attn[n,m]   -> [B,E,Nq]
    gemm_tf32_kernel<<<dim3(32, 2, 8), blk>>>(gv, attn, obuf, 1024,
        E * NKV, NQ * NKV, E * NQ,
        /*am*/1024, /*ak*/1, /*bk*/1, /*bn*/1024, /*cm*/4096, 1.0f);

    // 7) F = out_w @ O[b] -> second half of out (channels 256..511)
    gemm_tf32_kernel<<<dim3(32, 2, 8), blk>>>(ow, obuf, out + 256L * 4096, 256,
        0, E * NQ, 512L * 4096,
        /*am*/256, /*ak*/1, /*bk*/4096, /*bn*/1, /*cm*/4096, 1.0f);

    // 8) concat: copy C into first half of out
    copy_c_kernel<<<8192, blk>>>((const float4*)C, (float4*)out);
}